// round 13
// baseline (speedup 1.0000x reference)
#include <cuda_runtime.h>
#include <cstdint>
#include <cstddef>

#define NN 3072
#define FB 512     // working block width (256 complex -> 512 real cols)
#define FOUT 256
#define FIN 512
#define NPACK 1280 // [wr1|wi1 | wr0|wi0 | w0]

// ---------------- scratch (device globals) -------------------------------------
__device__ __align__(1024) uint32_t g_adjp[(size_t)NN * NN / 2]; // bf16 fragment-tiled adj
__device__ __align__(1024) uint32_t g_Bbf[(NN / 2) * FB];        // bf16x2 interleaved B operand
__device__ __align__(1024) uint32_t g_xh[(size_t)NN * FIN / 2];  // x fragment-tiled bf16 hi
__device__ __align__(1024) uint32_t g_xl[(size_t)NN * FIN / 2];  // x fragment-tiled bf16 lo
__device__ __align__(1024) uint32_t g_wh[(FIN / 2) * NPACK];     // W pair-rows bf16 hi
__device__ __align__(1024) uint32_t g_wl[(FIN / 2) * NPACK];     // W pair-rows bf16 lo
__device__ __align__(128) float g_P[NN * NPACK];                 // packed projections
__device__ __align__(128) float g_Q[NN * FB];
__device__ __align__(128) float g_Y[NN * FB];
__device__ __align__(128) float g_XJ[NN * FB];
__device__ __align__(128) float g_G[3 * NN * FB];                // split-K partials
__device__ __align__(128) float g_dr[NN];
__device__ __align__(128) float g_di[NN];

// ---------------- helpers -------------------------------------------------------
__device__ __forceinline__ uint32_t packbf(float lo, float hi) {
    uint32_t d;
    asm("cvt.rn.bf16x2.f32 %0, %1, %2;" : "=r"(d) : "f"(hi), "f"(lo));
    return d;
}
__device__ __forceinline__ uint32_t packres(float lo, float hi, uint32_t h) {
    const float hl = __uint_as_float(h << 16);
    const float hh = __uint_as_float(h & 0xFFFF0000u);
    return packbf(lo - hl, hi - hh);
}
__device__ __forceinline__ uint32_t smem_u32(const void* p) {
    uint32_t a;
    asm("{ .reg .u64 t; cvta.to.shared.u64 t, %1; cvt.u32.u64 %0, t; }" : "=r"(a) : "l"(p));
    return a;
}
__device__ __forceinline__ void cpasync16(uint32_t dst, const void* src) {
    asm volatile("cp.async.cg.shared.global [%0], [%1], 16;" :: "r"(dst), "l"(src) : "memory");
}
__device__ __forceinline__ void mma16(float c[4],
                                      uint32_t a0, uint32_t a1, uint32_t a2, uint32_t a3,
                                      uint32_t b0, uint32_t b1) {
    asm volatile(
        "mma.sync.aligned.m16n8k16.row.col.f32.bf16.bf16.f32 "
        "{%0,%1,%2,%3}, {%4,%5,%6,%7}, {%8,%9}, {%0,%1,%2,%3};"
        : "+f"(c[0]), "+f"(c[1]), "+f"(c[2]), "+f"(c[3])
        : "r"(a0), "r"(a1), "r"(a2), "r"(a3), "r"(b0), "r"(b1));
}

// load 4 floats and sum the 3 split-K planes
__device__ __forceinline__ void add3v(const float* __restrict__ p, size_t P, float* o) {
    const float4 a = *(const float4*)p;
    const float4 b = *(const float4*)(p + P);
    const float4 c = *(const float4*)(p + 2 * P);
    o[0] = a.x + b.x + c.x;
    o[1] = a.y + b.y + c.y;
    o[2] = a.z + b.z + c.z;
    o[3] = a.w + b.w + c.w;
}
__device__ __forceinline__ void ld4(const float* __restrict__ p, float* o) {
    const float4 v = *(const float4*)p;
    o[0] = v.x; o[1] = v.y; o[2] = v.z; o[3] = v.w;
}
__device__ __forceinline__ void st4(float* __restrict__ p, const float* v) {
    *(float4*)p = make_float4(v[0], v[1], v[2], v[3]);
}

// ================= BIG GEMM: bf16-resident, cp.async 3-stage, BK=64 =============
__global__ void __launch_bounds__(256, 2)
gemm_big(const uint32_t* __restrict__ Ap, const uint32_t* __restrict__ Bbf,
         float* __restrict__ C, size_t cPlane) {
    constexpr int STAGE = 8576;
    extern __shared__ __align__(16) uint32_t sm[];
    const uint32_t smb = smem_u32(sm);

    const int tid  = threadIdx.x;
    const int lane = tid & 31;
    const int warp = tid >> 5;
    const int wrow = warp >> 2;
    const int wcol = warp & 3;
    const int g    = lane >> 2;
    const int t    = lane & 3;
    const int bMt  = blockIdx.y;
    const int bN   = blockIdx.x * 128;
    const int kt0  = blockIdx.z * 64;

    float acc[4][4][4];
#pragma unroll
    for (int i = 0; i < 4; i++)
#pragma unroll
        for (int j = 0; j < 4; j++)
#pragma unroll
            for (int k = 0; k < 4; k++) acc[i][j][k] = 0.f;

    auto issueStage = [&](int st, int s) {
        const uint32_t stb = smb + st * (STAGE * 4);
        const int kt16 = kt0 + s * 4;
        const size_t atile = ((size_t)bMt * 192 + kt16) * 1024;
#pragma unroll
        for (int i = 0; i < 4; i++) {
            const int c = tid + i * 256;
            const int j = c >> 8, w = c & 255;
            cpasync16(stb + (uint32_t)(j * 1056 + (w >> 6) * 264 + (w & 63) * 4) * 4,
                      Ap + atile + c * 4);
        }
        const size_t brow = (size_t)kt16 * 8 * FB + bN;
#pragma unroll
        for (int i = 0; i < 4; i++) {
            const int c = tid + i * 256;
            const int row = c >> 5, c4 = (c & 31) * 4;
            cpasync16(stb + 16896 + (uint32_t)(row * 136 + c4) * 4,
                      Bbf + brow + (size_t)row * FB + c4);
        }
        asm volatile("cp.async.commit_group;" ::: "memory");
    };

    const int nT = 16;
    issueStage(0, 0);
    issueStage(1, 1);

    for (int s = 0; s < nT; s++) {
        const int st = s % 3;
        if (s + 1 < nT) asm volatile("cp.async.wait_group 1;" ::: "memory");
        else            asm volatile("cp.async.wait_group 0;" ::: "memory");
        __syncthreads();
        if (s + 2 < nT) issueStage((s + 2) % 3, s + 2);

        const uint32_t* Abase = sm + st * STAGE + t * 264;
        const uint32_t* Bbase = sm + st * STAGE + 4224;
#pragma unroll
        for (int ks = 0; ks < 4; ks++) {
            uint4 afv[4];
            uint32_t bf[4][2];
#pragma unroll
            for (int mti = 0; mti < 4; mti++)
                afv[mti] = *(const uint4*)(Abase + ks * 1056 + ((wrow * 4 + mti) * 8 + g) * 4);
#pragma unroll
            for (int nt = 0; nt < 4; nt++) {
                const int n0 = wcol * 32 + nt * 8 + g;
                bf[nt][0] = Bbase[(ks * 8 + t) * 136 + n0];
                bf[nt][1] = Bbase[(ks * 8 + t + 4) * 136 + n0];
            }
#pragma unroll
            for (int mti = 0; mti < 4; mti++)
#pragma unroll
                for (int nt = 0; nt < 4; nt++)
                    mma16(acc[mti][nt], afv[mti].x, afv[mti].y, afv[mti].z, afv[mti].w,
                          bf[nt][0], bf[nt][1]);
        }
    }

    float* Ct = C + blockIdx.z * cPlane;
#pragma unroll
    for (int mti = 0; mti < 4; mti++) {
        const int row = bMt * 128 + wrow * 64 + mti * 16 + g;
#pragma unroll
        for (int nt = 0; nt < 4; nt++) {
            const int col = bN + wcol * 32 + nt * 8 + 2 * t;
            float* p = Ct + (size_t)row * FB + col;
            p[0]                  = acc[mti][nt][0];
            p[1]                  = acc[mti][nt][1];
            p[(size_t)8 * FB]     = acc[mti][nt][2];
            p[(size_t)8 * FB + 1] = acc[mti][nt][3];
        }
    }
}

// ================= projection GEMM (split-bf16, 3-stage) + fused packP2 ==========
__global__ void __launch_bounds__(256, 2)
gemm_proj(const uint32_t* __restrict__ Ah, const uint32_t* __restrict__ Al,
          const uint32_t* __restrict__ Bh, const uint32_t* __restrict__ Bl,
          float* __restrict__ C, uint32_t* __restrict__ Bout) {
    constexpr int AU = 2112;
    constexpr int BOFF = 4224;
    constexpr int BU = 16 * 136;
    constexpr int STAGE = BOFF + 2 * BU;

    extern __shared__ __align__(16) uint32_t sm[];
    const uint32_t smb = smem_u32(sm);

    const int tid  = threadIdx.x;
    const int lane = tid & 31;
    const int warp = tid >> 5;
    const int wrow = warp >> 2;
    const int wcol = warp & 3;
    const int g    = lane >> 2;
    const int t    = lane & 3;
    const int bMt  = blockIdx.y;
    const int bN   = blockIdx.x * 128;

    float acc[4][4][4];
#pragma unroll
    for (int i = 0; i < 4; i++)
#pragma unroll
        for (int j = 0; j < 4; j++)
#pragma unroll
            for (int k = 0; k < 4; k++) acc[i][j][k] = 0.f;

    auto issueStage = [&](int st, int s) {
        const uint32_t stb = smb + st * (STAGE * 4);
        const int kt16 = s * 2;
        const size_t atile = ((size_t)bMt * 32 + kt16) * 1024;
#pragma unroll
        for (int i = 0; i < 2; i++) {
            const int c = tid + i * 256;
            const int j = c >> 8, w = c & 255;
            const uint32_t off = (uint32_t)(j * 1056 + (w >> 6) * 264 + (w & 63) * 4) * 4;
            cpasync16(stb + off, Ah + atile + c * 4);
            cpasync16(stb + AU * 4 + off, Al + atile + c * 4);
        }
        const size_t brow = (size_t)kt16 * 8 * NPACK + bN;
#pragma unroll
        for (int i = 0; i < 2; i++) {
            const int c = tid + i * 256;
            const int row = c >> 5, c4 = (c & 31) * 4;
            const uint32_t off = (uint32_t)(row * 136 + c4) * 4;
            cpasync16(stb + BOFF * 4 + off, Bh + brow + (size_t)row * NPACK + c4);
            cpasync16(stb + (BOFF + BU) * 4 + off, Bl + brow + (size_t)row * NPACK + c4);
        }
        asm volatile("cp.async.commit_group;" ::: "memory");
    };

    const int nT = 16;
    issueStage(0, 0);
    issueStage(1, 1);

    for (int s = 0; s < nT; s++) {
        const int st = s % 3;
        if (s + 1 < nT) asm volatile("cp.async.wait_group 1;" ::: "memory");
        else            asm volatile("cp.async.wait_group 0;" ::: "memory");
        __syncthreads();
        if (s + 2 < nT) issueStage((s + 2) % 3, s + 2);

        const uint32_t* Sb = sm + st * STAGE;
        const uint32_t* Abase = Sb + t * 264;
        const uint32_t* Bbase = Sb + BOFF;
#pragma unroll
        for (int ks = 0; ks < 2; ks++) {
            uint4 afh[4], afl[4];
            uint32_t bfh[4][2], bfl[4][2];
#pragma unroll
            for (int mti = 0; mti < 4; mti++) {
                afh[mti] = *(const uint4*)(Abase + ks * 1056 + ((wrow * 4 + mti) * 8 + g) * 4);
                afl[mti] = *(const uint4*)(Abase + AU + ks * 1056 + ((wrow * 4 + mti) * 8 + g) * 4);
            }
#pragma unroll
            for (int nt = 0; nt < 4; nt++) {
                const int n0 = wcol * 32 + nt * 8 + g;
                bfh[nt][0] = Bbase[(ks * 8 + t) * 136 + n0];
                bfh[nt][1] = Bbase[(ks * 8 + t + 4) * 136 + n0];
                bfl[nt][0] = Bbase[BU + (ks * 8 + t) * 136 + n0];
                bfl[nt][1] = Bbase[BU + (ks * 8 + t + 4) * 136 + n0];
            }
#pragma unroll
            for (int mti = 0; mti < 4; mti++)
#pragma unroll
                for (int nt = 0; nt < 4; nt++) {
                    mma16(acc[mti][nt], afh[mti].x, afh[mti].y, afh[mti].z, afh[mti].w,
                          bfl[nt][0], bfl[nt][1]);
                    mma16(acc[mti][nt], afl[mti].x, afl[mti].y, afl[mti].z, afl[mti].w,
                          bfh[nt][0], bfh[nt][1]);
                    mma16(acc[mti][nt], afh[mti].x, afh[mti].y, afh[mti].z, afh[mti].w,
                          bfh[nt][0], bfh[nt][1]);
                }
        }
    }

#pragma unroll
    for (int mti = 0; mti < 4; mti++) {
        const int row = bMt * 128 + wrow * 64 + mti * 16 + g;
#pragma unroll
        for (int nt = 0; nt < 4; nt++) {
            const int col = bN + wcol * 32 + nt * 8 + 2 * t;
            float* p = C + (size_t)row * NPACK + col;
            p[0]                     = acc[mti][nt][0];
            p[1]                     = acc[mti][nt][1];
            p[(size_t)8 * NPACK]     = acc[mti][nt][2];
            p[(size_t)8 * NPACK + 1] = acc[mti][nt][3];
        }
    }

    if (blockIdx.x < 4) {
#pragma unroll
        for (int mti = 0; mti < 4; mti++) {
            const int row = bMt * 128 + wrow * 64 + mti * 16 + g;
#pragma unroll
            for (int nt = 0; nt < 4; nt++) {
                const int col = bN + wcol * 32 + nt * 8 + 2 * t;
                const float v00 = acc[mti][nt][0], v01 = acc[mti][nt][1];
                const float v10 = acc[mti][nt][2], v11 = acc[mti][nt][3];
                const float o00 = __shfl_xor_sync(0xffffffffu, v00, 4);
                const float o01 = __shfl_xor_sync(0xffffffffu, v01, 4);
                const float o10 = __shfl_xor_sync(0xffffffffu, v10, 4);
                const float o11 = __shfl_xor_sync(0xffffffffu, v11, 4);
                if (!(g & 1)) {
                    *(uint2*)&Bout[(size_t)(row >> 1) * FB + col] =
                        make_uint2(packbf(v00, o00), packbf(v01, o01));
                    *(uint2*)&Bout[(size_t)((row + 8) >> 1) * FB + col] =
                        make_uint2(packbf(v10, o10), packbf(v11, o11));
                }
            }
        }
    }
}

// ---------------- merged prep kernel ----------------------------------------------
__device__ __forceinline__ float wallVal(const float* __restrict__ w0,
                                         const float* __restrict__ wr,
                                         const float* __restrict__ wi, int r, int c) {
    if (c < 256)       return wr[(size_t)FIN * FOUT + (size_t)r * FOUT + c];
    if (c < 512)       return wi[(size_t)FIN * FOUT + (size_t)r * FOUT + (c - 256)];
    if (c < 768)       return wr[(size_t)r * FOUT + (c - 512)];
    if (c < 1024)      return wi[(size_t)r * FOUT + (c - 768)];
    return w0[(size_t)r * FOUT + (c - 1024)];
}

__device__ __forceinline__ void packFragRow(const float* __restrict__ src, int K,
                                            uint32_t* __restrict__ dsth,
                                            uint32_t* __restrict__ dstl,
                                            int ktiles, int kt, int mt, int tp) {
    const int mloc = tp >> 1, half = tp & 1;
    const float* s = src + (size_t)(mt * 128 + mloc) * K + kt * 16 + half * 8;
    const float4 v0 = *(const float4*)s;
    const float4 v1 = *(const float4*)(s + 4);
    const float v[8] = {v0.x, v0.y, v0.z, v0.w, v1.x, v1.y, v1.z, v1.w};
    const int mg   = (mloc & 7) | ((mloc >> 4) << 3);
    const int msel = (mloc >> 3) & 1;
    const int reg  = half * 2 + msel;
    const size_t base = ((size_t)mt * ktiles + kt) * 1024 + mg * 4 + reg;
#pragma unroll
    for (int tt = 0; tt < 4; tt++) {
        const uint32_t h = packbf(v[2 * tt], v[2 * tt + 1]);
        dsth[base + tt * 256] = h;
        if (dstl) dstl[base + tt * 256] = packres(v[2 * tt], v[2 * tt + 1], h);
    }
}

__global__ void prep_kernel(const float* __restrict__ adj, const float* __restrict__ hp,
                            const float* __restrict__ x,
                            const float* __restrict__ w0, const float* __restrict__ wr,
                            const float* __restrict__ wi) {
    const int b = blockIdx.x;
    if (b < 3072) {
        __shared__ float sh[256];
        const float* a = adj + (size_t)b * NN;
        float s = 0.f;
        for (int c = threadIdx.x; c < NN; c += 256) s += a[c];
        sh[threadIdx.x] = s;
        __syncthreads();
        for (int o = 128; o > 0; o >>= 1) {
            if (threadIdx.x < o) sh[threadIdx.x] += sh[threadIdx.x + o];
            __syncthreads();
        }
        if (threadIdx.x == 0) {
            const float h = *hp;
            const float sv = h * (1.0f - sh[0]);
            const float inv = 1.0f / (sv * sv + 1.0f);
            g_dr[b] = sv * inv;
            g_di[b] = -inv;
        }
    } else if (b < 4352) {
        const int i = (b - 3072) * 256 + threadIdx.x;
        const int r = i / NPACK;
        const int c = i % NPACK;
        const float v0 = wallVal(w0, wr, wi, 2 * r, c);
        const float v1 = wallVal(w0, wr, wi, 2 * r + 1, c);
        const uint32_t h = packbf(v0, v1);
        g_wh[i] = h;
        g_wl[i] = packres(v0, v1, h);
    } else if (b < 5120) {
        const int p = b - 4352;
        packFragRow(x, FIN, g_xh, g_xl, 32, p & 31, p >> 5, threadIdx.x);
    } else {
        const int p = b - 5120;
        packFragRow(adj, NN, g_adjp, nullptr, 192, p % 192, p / 192, threadIdx.x);
    }
}

// ---------------- elementwise kernels (vectorized, 4 cols per thread) -------------

// xj: XJ = (hL - iI)@Qsrc ; Bbf = bf16(XJ). Y NOT written (first jacobi uses XJ).
__global__ void __launch_bounds__(256)
xj_kernel(const float* __restrict__ hp, const float* __restrict__ Qsrc, int ldq) {
    const int i = blockIdx.x * 256 + threadIdx.x;   // 0..98303
    const int r = i >> 6;                           // pair row 0..1535
    const int c0 = (i & 63) * 4;                    // column base (complex idx)
    const int n0 = 2 * r, n1 = n0 + 1;
    const float h = *hp;
    const size_t P = (size_t)NN * FB;
    const size_t i0r = (size_t)n0 * FB + c0, i0i = i0r + 256;
    const size_t i1r = (size_t)n1 * FB + c0, i1i = i1r + 256;

    float GR0[4], GI0[4], GR1[4], GI1[4];
    add3v(g_G + i0r, P, GR0); add3v(g_G + i0i, P, GI0);
    add3v(g_G + i1r, P, GR1); add3v(g_G + i1i, P, GI1);
    float q0r[4], q0i[4], q1r[4], q1i[4];
    ld4(Qsrc + (size_t)n0 * ldq + c0, q0r); ld4(Qsrc + (size_t)n0 * ldq + c0 + 256, q0i);
    ld4(Qsrc + (size_t)n1 * ldq + c0, q1r); ld4(Qsrc + (size_t)n1 * ldq + c0 + 256, q1i);

    float x0r[4], x0i[4], x1r[4], x1i[4];
    uint32_t br[4], bi[4];
#pragma unroll
    for (int u = 0; u < 4; u++) {
        x0r[u] = h * q0r[u] - h * GR0[u] + q0i[u];
        x0i[u] = h * q0i[u] - h * GI0[u] - q0r[u];
        x1r[u] = h * q1r[u] - h * GR1[u] + q1i[u];
        x1i[u] = h * q1i[u] - h * GI1[u] - q1r[u];
        br[u] = packbf(x0r[u], x1r[u]);
        bi[u] = packbf(x0i[u], x1i[u]);
    }
    st4(g_XJ + i0r, x0r); st4(g_XJ + i0i, x0i);
    st4(g_XJ + i1r, x1r); st4(g_XJ + i1i, x1i);
    *(uint4*)&g_Bbf[(size_t)r * FB + c0]       = make_uint4(br[0], br[1], br[2], br[3]);
    *(uint4*)&g_Bbf[(size_t)r * FB + c0 + 256] = make_uint4(bi[0], bi[1], bi[2], bi[3]);
}

// MODE 0: normal. MODE 1: formQ-fused. MODE 2: last (relu out). FIRST: Y==XJ.
template <int MODE, int FIRST>
__global__ void __launch_bounds__(256)
jacobi_kernel(const float* __restrict__ hp,
              const float* __restrict__ dr, const float* __restrict__ di,
              float* __restrict__ out) {
    const int i = blockIdx.x * 256 + threadIdx.x;
    const int r = i >> 6;
    const int c0 = (i & 63) * 4;
    const int n0 = 2 * r, n1 = n0 + 1;
    const float h = *hp;
    const size_t P = (size_t)NN * FB;
    const size_t i0r = (size_t)n0 * FB + c0, i0i = i0r + 256;
    const size_t i1r = (size_t)n1 * FB + c0, i1i = i1r + 256;

    float GR0[4], GI0[4], GR1[4], GI1[4];
    add3v(g_G + i0r, P, GR0); add3v(g_G + i0i, P, GI0);
    add3v(g_G + i1r, P, GR1); add3v(g_G + i1i, P, GI1);
    float x0r[4], x0i[4], x1r[4], x1i[4];
    ld4(g_XJ + i0r, x0r); ld4(g_XJ + i0i, x0i);
    ld4(g_XJ + i1r, x1r); ld4(g_XJ + i1i, x1i);
    float y0r[4], y0i[4], y1r[4], y1i[4];
    if (FIRST) {
#pragma unroll
        for (int u = 0; u < 4; u++) {
            y0r[u] = x0r[u]; y0i[u] = x0i[u];
            y1r[u] = x1r[u]; y1i[u] = x1i[u];
        }
    } else {
        ld4(g_Y + i0r, y0r); ld4(g_Y + i0i, y0i);
        ld4(g_Y + i1r, y1r); ld4(g_Y + i1i, y1i);
    }
    const float d0r = dr[n0], d0i = di[n0];
    const float d1r = dr[n1], d1i = di[n1];

    float ny0r[4], ny0i[4], ny1r[4], ny1i[4];
#pragma unroll
    for (int u = 0; u < 4; u++) {
        const float r0r = x0r[u] - (h * y0r[u] - h * GR0[u] - y0i[u]);
        const float r0i = x0i[u] - (h * y0i[u] - h * GI0[u] + y0r[u]);
        const float r1r = x1r[u] - (h * y1r[u] - h * GR1[u] - y1i[u]);
        const float r1i = x1i[u] - (h * y1i[u] - h * GI1[u] + y1r[u]);
        ny0r[u] = y0r[u] + d0r * r0r - d0i * r0i;
        ny0i[u] = y0i[u] + d0r * r0i + d0i * r0r;
        ny1r[u] = y1r[u] + d1r * r1r - d1i * r1i;
        ny1i[u] = y1i[u] + d1r * r1i + d1i * r1r;
    }

    if (MODE == 2) {
        float p0[4], p1[4], v0[4], v1[4];
        ld4(g_P + (size_t)n0 * NPACK + 1024 + c0, p0);
        ld4(g_P + (size_t)n1 * NPACK + 1024 + c0, p1);
#pragma unroll
        for (int u = 0; u < 4; u++) {
            const float a = p0[u] + 2.f * ny0r[u];
            const float b = p1[u] + 2.f * ny1r[u];
            v0[u] = a > 0.f ? a : 0.f;
            v1[u] = b > 0.f ? b : 0.f;
        }
        st4(out + (size_t)n0 * FOUT + c0, v0);
        st4(out + (size_t)n1 * FOUT + c0, v1);
    } else if (MODE == 1) {
        float p0r[4], p0i[4], p1r[4], p1i[4];
        ld4(g_P + (size_t)n0 * NPACK + 512 + c0, p0r);
        ld4(g_P + (size_t)n0 * NPACK + 768 + c0, p0i);
        ld4(g_P + (size_t)n1 * NPACK + 512 + c0, p1r);
        ld4(g_P + (size_t)n1 * NPACK + 768 + c0, p1i);
        float q0r[4], q0i[4], q1r[4], q1i[4];
        uint32_t br[4], bi[4];
#pragma unroll
        for (int u = 0; u < 4; u++) {
            q0r[u] = p0r[u] + ny0r[u]; q0i[u] = p0i[u] + ny0i[u];
            q1r[u] = p1r[u] + ny1r[u]; q1i[u] = p1i[u] + ny1i[u];
            br[u] = packbf(q0r[u], q1r[u]);
            bi[u] = packbf(q0i[u], q1i[u]);
        }
        st4(g_Q + i0r, q0r); st4(g_Q + i0i, q0i);
        st4(g_Q + i1r, q1r); st4(g_Q + i1i, q1i);
        *(uint4*)&g_Bbf[(size_t)r * FB + c0]       = make_uint4(br[0], br[1], br[2], br[3]);
        *(uint4*)&g_Bbf[(size_t)r * FB + c0 + 256] = make_uint4(bi[0], bi[1], bi[2], bi[3]);
    } else {
        uint32_t br[4], bi[4];
#pragma unroll
        for (int u = 0; u < 4; u++) {
            br[u] = packbf(ny0r[u], ny1r[u]);
            bi[u] = packbf(ny0i[u], ny1i[u]);
        }
        st4(g_Y + i0r, ny0r); st4(g_Y + i0i, ny0i);
        st4(g_Y + i1r, ny1r); st4(g_Y + i1i, ny1i);
        *(uint4*)&g_Bbf[(size_t)r * FB + c0]       = make_uint4(br[0], br[1], br[2], br[3]);
        *(uint4*)&g_Bbf[(size_t)r * FB + c0 + 256] = make_uint4(bi[0], bi[1], bi[2], bi[3]);
    }
}

// ---------------- orchestration --------------------------------------------------
#define SMEM_BIG   (3 * 8576 * 4)
#define SMEM_PROJ  (3 * 8576 * 4)
#define EW_GRID    384

extern "C" void kernel_launch(void* const* d_in, const int* in_sizes, int n_in,
                              void* d_out, int out_size) {
    const float* x   = (const float*)d_in[0];
    const float* adj = (const float*)d_in[1];
    const float* hp  = (const float*)d_in[2];
    const float* w0  = (const float*)d_in[3];
    const float* wr  = (const float*)d_in[4];
    const float* wi  = (const float*)d_in[5];
    float* out = (float*)d_out;

    float *Pp, *Q, *G, *dr, *di;
    uint32_t *adjp, *Bbf, *xh, *xl, *wh, *wl;
    cudaGetSymbolAddress((void**)&Pp, g_P);
    cudaGetSymbolAddress((void**)&Q, g_Q);
    cudaGetSymbolAddress((void**)&G, g_G);
    cudaGetSymbolAddress((void**)&dr, g_dr);
    cudaGetSymbolAddress((void**)&di, g_di);
    cudaGetSymbolAddress((void**)&adjp, g_adjp);
    cudaGetSymbolAddress((void**)&Bbf, g_Bbf);
    cudaGetSymbolAddress((void**)&xh, g_xh);
    cudaGetSymbolAddress((void**)&xl, g_xl);
    cudaGetSymbolAddress((void**)&wh, g_wh);
    cudaGetSymbolAddress((void**)&wl, g_wl);

    cudaFuncSetAttribute(gemm_big,  cudaFuncAttributeMaxDynamicSharedMemorySize, SMEM_BIG);
    cudaFuncSetAttribute(gemm_proj, cudaFuncAttributeMaxDynamicSharedMemorySize, SMEM_PROJ);

    // merged prep: rowsum + packW(hi/lo) + packX + packAdj
    prep_kernel<<<9728, 256>>>(adj, hp, x, w0, wr, wi);

    // P = x @ WALL (split-bf16, fp32-grade); P2 cols also emit Bbf directly
    gemm_proj<<<dim3(10, 24, 1), 256, SMEM_PROJ>>>(xh, xl, wh, wl, Pp, Bbf);

    const dim3 gridBig(4, 24, 3);
    const size_t PL = (size_t)NN * FB;

    // applyK #1: Y = K @ P2 ; last jacobi fuses Q = P1 + Y
    gemm_big<<<gridBig, 256, SMEM_BIG>>>(adjp, Bbf, G, PL);
    xj_kernel<<<EW_GRID, 256>>>(hp, Pp, NPACK);
    gemm_big<<<gridBig, 256, SMEM_BIG>>>(adjp, Bbf, G, PL);
    jacobi_kernel<0, 1><<<EW_GRID, 256>>>(hp, dr, di, out);
    gemm_big<<<gridBig, 256, SMEM_BIG>>>(adjp, Bbf, G, PL);
    jacobi_kernel<0, 0><<<EW_GRID, 256>>>(hp, dr, di, out);
    gemm_big<<<gridBig, 256, SMEM_BIG>>>(adjp, Bbf, G, PL);
    jacobi_kernel<1, 0><<<EW_GRID, 256>>>(hp, dr, di, out);   // formQ fused

    // applyK #2: Y = K @ Q ; last jacobi fuses relu
    gemm_big<<<gridBig, 256, SMEM_BIG>>>(adjp, Bbf, G, PL);
    xj_kernel<<<EW_GRID, 256>>>(hp, Q, FB);
    gemm_big<<<gridBig, 256, SMEM_BIG>>>(adjp, Bbf, G, PL);
    jacobi_kernel<0, 1><<<EW_GRID, 256>>>(hp, dr, di, out);
    gemm_big<<<gridBig, 256, SMEM_BIG>>>(adjp, Bbf, G, PL);
    jacobi_kernel<0, 0><<<EW_GRID, 256>>>(hp, dr, di, out);
    gemm_big<<<gridBig, 256, SMEM_BIG>>>(adjp, Bbf, G, PL);
    jacobi_kernel<2, 0><<<EW_GRID, 256>>>(hp, dr, di, out);   // relu fused
}